// round 4
// baseline (speedup 1.0000x reference)
#include <cuda_runtime.h>
#include <cstdint>

// T=8192, B=512, H=16, IN=1, OUT=5; output = FC(GRU hidden of batch index 511).
#define T_LEN 8192
#define BATCH 512
#define HID   16
#define NOUT  5

__device__ float g_hist[T_LEN * HID];

__device__ __forceinline__ float tanhap(float x) {
    float y; asm("tanh.approx.f32 %0, %1;" : "=f"(y) : "f"(x)); return y;
}
__device__ __forceinline__ unsigned long long pk2(float lo, float hi) {
    unsigned long long r; asm("mov.b64 %0, {%1, %2};" : "=l"(r) : "f"(lo), "f"(hi)); return r;
}
__device__ __forceinline__ void upk2(float& lo, float& hi, unsigned long long v) {
    asm("mov.b64 {%0, %1}, %2;" : "=f"(lo), "=f"(hi) : "l"(v));
}
__device__ __forceinline__ unsigned long long fma2(unsigned long long a, unsigned long long b,
                                                   unsigned long long c) {
    unsigned long long d;
    asm("fma.rn.f32x2 %0, %1, %2, %3;" : "=l"(d) : "l"(a), "l"(b), "l"(c));
    return d;
}
__device__ __forceinline__ unsigned long long add2(unsigned long long a, unsigned long long b) {
    unsigned long long d;
    asm("add.rn.f32x2 %0, %1, %2;" : "=l"(d) : "l"(a), "l"(b));
    return d;
}

__global__ void __launch_bounds__(32, 1)
gru_seq_kernel(const float* __restrict__ x,
               const float* __restrict__ w_ih,
               const float* __restrict__ w_hh,
               const float* __restrict__ b_ih,
               const float* __restrict__ b_hh)
{
    const unsigned FULL = 0xffffffffu;
    const int lane = threadIdx.x;
    const int j    = lane & 15;
    const bool low = lane < 16;

    // sigmoid(v) = 0.5 + 0.5*tanh(v/2): gate rows pre-halved.
    // Lane split: dotA row = r-row j (low lanes) / z-row j (high lanes).
    // dotB row = n-row j (both halves; whh_n/bhh_n halved:
    //   narg = xg_n + hg_n/2 + tanh(garg_r/2) * (hg_n/2)).
    const int rowA = low ? j : (HID + j);

    unsigned long long wA[8], wn[8];
    #pragma unroll
    for (int k = 0; k < 8; ++k) {
        const float* ra = &w_hh[rowA * HID];
        const float* rn = &w_hh[(2 * HID + j) * HID];
        wA[k] = pk2(0.5f * ra[2 * k], 0.5f * ra[2 * k + 1]);
        wn[k] = pk2(0.5f * rn[2 * k], 0.5f * rn[2 * k + 1]);
    }
    const float wihA2  = 0.5f * w_ih[rowA];
    const float biasA2 = 0.5f * (b_ih[rowA] + b_hh[rowA]);
    const float wih_n  = w_ih[2 * HID + j];
    const float bih_n  = b_ih[2 * HID + j];
    const unsigned long long bn2pk = pk2(0.5f * b_hh[2 * HID + j], 0.0f);
    const unsigned long long Z64 = 0ull;

    // Replicated hidden state, packed f32x2: h[k] = (h_{2k}, h_{2k+1}).
    unsigned long long h[8];
    #pragma unroll
    for (int k = 0; k < 8; ++k) h[k] = 0ull;
    float h_own = 0.0f;   // valid on low lanes

    float* hist = &g_hist[j];

    const int xoff = BATCH - 1;
    float xv      = x[(0  + lane) * BATCH + xoff];
    float xv_next = x[(32 + lane) * BATCH + xoff];

    const int NCHUNK = T_LEN / 32;
    for (int c = 0; c < NCHUNK; ++c) {
        #pragma unroll 4
        for (int s = 0; s < 32; ++s) {
            const float xt  = __shfl_sync(FULL, xv, s);
            const float xgA = fmaf(xt, wihA2, biasA2);
            const float xgn = fmaf(xt, wih_n, bih_n);

            // two 16-dots: dotA (r|z by lane half), dotB (n). 2 acc chains each.
            unsigned long long aA0, aA1, aN0, aN1;
            aA0 = fma2(wA[0], h[0], Z64);   aN0 = fma2(wn[0], h[0], bn2pk);
            aA1 = fma2(wA[1], h[1], Z64);   aN1 = fma2(wn[1], h[1], Z64);
            aA0 = fma2(wA[2], h[2], aA0);   aN0 = fma2(wn[2], h[2], aN0);
            aA1 = fma2(wA[3], h[3], aA1);   aN1 = fma2(wn[3], h[3], aN1);
            aA0 = fma2(wA[4], h[4], aA0);   aN0 = fma2(wn[4], h[4], aN0);
            aA1 = fma2(wA[5], h[5], aA1);   aN1 = fma2(wn[5], h[5], aN1);
            aA0 = fma2(wA[6], h[6], aA0);   aN0 = fma2(wn[6], h[6], aN0);
            aA1 = fma2(wA[7], h[7], aA1);   aN1 = fma2(wn[7], h[7], aN1);

            float lo, hi;
            upk2(lo, hi, add2(aA0, aA1)); const float hgA2 = lo + hi;
            upk2(lo, hi, add2(aN0, aN1)); const float hgn2 = lo + hi;

            // gate tanh: low lanes -> t_r, high lanes -> t_z (one MUFU)
            const float t  = tanhap(xgA + hgA2);
            const float tz = __shfl_xor_sync(FULL, t, 16);   // low: t_z

            const float narg = fmaf(t, hgn2, xgn + hgn2);    // t == t_r on low
            const float n    = tanhap(narg);
            const float zg   = fmaf(0.5f, tz, 0.5f);
            const float hn   = fmaf(zg, h_own - n, n);       // valid on low lanes
            h_own = hn;

            // broadcast new h from lanes 0..15, packed into f32x2 pairs
            {
                const float e0  = __shfl_sync(FULL, hn, 0);
                const float e1  = __shfl_sync(FULL, hn, 1);
                const float e2  = __shfl_sync(FULL, hn, 2);
                const float e3  = __shfl_sync(FULL, hn, 3);
                const float e4  = __shfl_sync(FULL, hn, 4);
                const float e5  = __shfl_sync(FULL, hn, 5);
                const float e6  = __shfl_sync(FULL, hn, 6);
                const float e7  = __shfl_sync(FULL, hn, 7);
                const float e8  = __shfl_sync(FULL, hn, 8);
                const float e9  = __shfl_sync(FULL, hn, 9);
                const float e10 = __shfl_sync(FULL, hn, 10);
                const float e11 = __shfl_sync(FULL, hn, 11);
                const float e12 = __shfl_sync(FULL, hn, 12);
                const float e13 = __shfl_sync(FULL, hn, 13);
                const float e14 = __shfl_sync(FULL, hn, 14);
                const float e15 = __shfl_sync(FULL, hn, 15);
                h[0] = pk2(e0,  e1);
                h[1] = pk2(e2,  e3);
                h[2] = pk2(e4,  e5);
                h[3] = pk2(e6,  e7);
                h[4] = pk2(e8,  e9);
                h[5] = pk2(e10, e11);
                h[6] = pk2(e12, e13);
                h[7] = pk2(e14, e15);
            }

            if (low) *hist = hn;
            hist += HID;
        }
        xv = xv_next;
        if (c + 2 < NCHUNK) xv_next = x[((c + 2) * 32 + lane) * BATCH + xoff];
    }
}

// out[t][o] = h_t . fc_w[o] + fc_b[o]
__global__ void fc_kernel(const float* __restrict__ fc_w,
                          const float* __restrict__ fc_b,
                          float* __restrict__ out)
{
    const int i = blockIdx.x * blockDim.x + threadIdx.x;
    if (i >= T_LEN * NOUT) return;
    const int t = i / NOUT;
    const int o = i - t * NOUT;
    const float* hrow = &g_hist[t * HID];
    float acc = fc_b[o];
    #pragma unroll
    for (int k = 0; k < HID; ++k)
        acc = fmaf(hrow[k], fc_w[o * HID + k], acc);
    out[i] = acc;
}

extern "C" void kernel_launch(void* const* d_in, const int* in_sizes, int n_in,
                              void* d_out, int out_size)
{
    const float* x    = (const float*)d_in[0];
    const float* w_ih = (const float*)d_in[1];
    const float* w_hh = (const float*)d_in[2];
    const float* b_ih = (const float*)d_in[3];
    const float* b_hh = (const float*)d_in[4];
    const float* fc_w = (const float*)d_in[5];
    const float* fc_b = (const float*)d_in[6];
    float* out = (float*)d_out;

    gru_seq_kernel<<<1, 32>>>(x, w_ih, w_hh, b_ih, b_hh);

    const int n = T_LEN * NOUT;
    fc_kernel<<<(n + 255) / 256, 256>>>(fc_w, fc_b, out);
}

// round 5
// speedup vs baseline: 1.2007x; 1.2007x over previous
#include <cuda_runtime.h>
#include <cstdint>

// T=8192, B=512, H=16, IN=1, OUT=5; output = FC(GRU hidden of batch index 511).
#define T_LEN 8192
#define BATCH 512
#define HID   16
#define NOUT  5

__device__ float g_hist[T_LEN * HID];

__device__ __forceinline__ float tanhap(float x) {
    float y; asm("tanh.approx.f32 %0, %1;" : "=f"(y) : "f"(x)); return y;
}
__device__ __forceinline__ unsigned long long pk2(float lo, float hi) {
    unsigned long long r; asm("mov.b64 %0, {%1, %2};" : "=l"(r) : "f"(lo), "f"(hi)); return r;
}
__device__ __forceinline__ void upk2(float& lo, float& hi, unsigned long long v) {
    asm("mov.b64 {%0, %1}, %2;" : "=f"(lo), "=f"(hi) : "l"(v));
}
__device__ __forceinline__ unsigned long long fma2(unsigned long long a, unsigned long long b,
                                                   unsigned long long c) {
    unsigned long long d;
    asm("fma.rn.f32x2 %0, %1, %2, %3;" : "=l"(d) : "l"(a), "l"(b), "l"(c));
    return d;
}
__device__ __forceinline__ unsigned long long add2(unsigned long long a, unsigned long long b) {
    unsigned long long d;
    asm("add.rn.f32x2 %0, %1, %2;" : "=l"(d) : "l"(a), "l"(b));
    return d;
}

__global__ void __launch_bounds__(32, 1)
gru_seq_kernel(const float* __restrict__ x,
               const float* __restrict__ w_ih,
               const float* __restrict__ w_hh,
               const float* __restrict__ b_ih,
               const float* __restrict__ b_hh)
{
    __shared__ __align__(16) float hbuf[16];
    const unsigned FULL = 0xffffffffu;
    const int lane = threadIdx.x;
    const int j    = lane & 15;   // lanes j and j+16 do identical work (r,z,n all local)

    // sigmoid(v) = 0.5 + 0.5*tanh(v/2): r/z rows pre-halved.
    // n: narg = xg_n + hg_n/2 + tanh(garg_r/2)*(hg_n/2): whh_n/bhh_n halved.
    unsigned long long wr[8], wz[8], wn[8];
    #pragma unroll
    for (int k = 0; k < 8; ++k) {
        const float* rr = &w_hh[j * HID];
        const float* rz = &w_hh[(HID + j) * HID];
        const float* rn = &w_hh[(2 * HID + j) * HID];
        wr[k] = pk2(0.5f * rr[2 * k], 0.5f * rr[2 * k + 1]);
        wz[k] = pk2(0.5f * rz[2 * k], 0.5f * rz[2 * k + 1]);
        wn[k] = pk2(0.5f * rn[2 * k], 0.5f * rn[2 * k + 1]);
    }
    const float wih_r2  = 0.5f * w_ih[j];
    const float bias_r2 = 0.5f * (b_ih[j] + b_hh[j]);
    const float wih_z2  = 0.5f * w_ih[HID + j];
    const float bias_z2 = 0.5f * (b_ih[HID + j] + b_hh[HID + j]);
    const float wih_n   = w_ih[2 * HID + j];
    const float bih_n   = b_ih[2 * HID + j];
    const unsigned long long bn2pk = pk2(0.5f * b_hh[2 * HID + j], 0.0f);
    const unsigned long long Z64 = 0ull;

    if (lane < 16) hbuf[j] = 0.0f;
    __syncwarp();
    float h_own = 0.0f;

    uint32_t sbase;
    asm("{ .reg .u64 t; cvta.to.shared.u64 t, %1; cvt.u32.u64 %0, t; }"
        : "=r"(sbase) : "l"(&hbuf[0]));
    const uint32_t waddr = sbase + (uint32_t)(j * 4);

    // All 32 lanes store (lanes j and j+16 write the same value to the same
    // address) — no predication anywhere in the loop body, no divergence.
    float* histp = &g_hist[j];

    const int xoff = BATCH - 1;
    float xv      = x[(0  + lane) * BATCH + xoff];
    float xv_next = x[(32 + lane) * BATCH + xoff];

    const int NCHUNK = T_LEN / 32;
    for (int c = 0; c < NCHUNK; ++c) {
        #pragma unroll
        for (int s = 0; s < 32; ++s) {
            // Warp-synchronous single-buffer roundtrip: the STS at the end of
            // the previous step precedes these LDS in program order; the smem
            // pipeline is in-order per warp.
            unsigned long long h0, h1, h2, h3, h4, h5, h6, h7;
            asm volatile("ld.shared.v2.u64 {%0, %1}, [%2];" : "=l"(h0), "=l"(h1) : "r"(sbase));
            asm volatile("ld.shared.v2.u64 {%0, %1}, [%2];" : "=l"(h2), "=l"(h3) : "r"(sbase + 16));
            asm volatile("ld.shared.v2.u64 {%0, %1}, [%2];" : "=l"(h4), "=l"(h5) : "r"(sbase + 32));
            asm volatile("ld.shared.v2.u64 {%0, %1}, [%2];" : "=l"(h6), "=l"(h7) : "r"(sbase + 48));

            const float xt  = __shfl_sync(FULL, xv, s);
            const float xgr = fmaf(xt, wih_r2, bias_r2);
            const float xgz = fmaf(xt, wih_z2, bias_z2);
            const float xgn = fmaf(xt, wih_n,  bih_n);

            unsigned long long ar0, ar1, az0, az1, an0, an1;
            ar0 = fma2(wr[0], h0, Z64);   an0 = fma2(wn[0], h0, bn2pk);
            ar1 = fma2(wr[1], h1, Z64);   an1 = fma2(wn[1], h1, Z64);
            az0 = fma2(wz[0], h0, Z64);   az1 = fma2(wz[1], h1, Z64);
            ar0 = fma2(wr[2], h2, ar0);   an0 = fma2(wn[2], h2, an0);
            ar1 = fma2(wr[3], h3, ar1);   an1 = fma2(wn[3], h3, an1);
            az0 = fma2(wz[2], h2, az0);   az1 = fma2(wz[3], h3, az1);
            ar0 = fma2(wr[4], h4, ar0);   an0 = fma2(wn[4], h4, an0);
            ar1 = fma2(wr[5], h5, ar1);   an1 = fma2(wn[5], h5, an1);
            az0 = fma2(wz[4], h4, az0);   az1 = fma2(wz[5], h5, az1);
            ar0 = fma2(wr[6], h6, ar0);   an0 = fma2(wn[6], h6, an0);
            ar1 = fma2(wr[7], h7, ar1);   an1 = fma2(wn[7], h7, an1);
            az0 = fma2(wz[6], h6, az0);   az1 = fma2(wz[7], h7, az1);

            float lo, hi;
            upk2(lo, hi, add2(ar0, ar1)); const float hg_r2 = lo + hi;
            upk2(lo, hi, add2(an0, an1)); const float hg_n2 = lo + hi;
            upk2(lo, hi, add2(az0, az1)); const float hg_z2 = lo + hi;

            const float t_r = tanhap(xgr + hg_r2);
            const float t_z = tanhap(xgz + hg_z2);
            // zg = 0.5 + 0.5*t_z ; omz = 1 - zg ; both off the n-path
            const float zg  = fmaf(0.5f, t_z, 0.5f);
            const float omz = fmaf(-0.5f, t_z, 0.5f);
            const float zh  = zg * h_own;

            const float narg = fmaf(t_r, hg_n2, xgn + hg_n2);
            const float n    = tanhap(narg);
            const float hn   = fmaf(n, omz, zh);   // single FMA after tanh_n
            h_own = hn;

            asm volatile("st.shared.f32 [%0], %1;" :: "r"(waddr), "f"(hn));
            *histp = hn;
            histp += HID;
        }
        xv = xv_next;
        const int nc = (c + 2 < NCHUNK) ? (c + 2) : (NCHUNK - 1);   // branch-free
        xv_next = x[(nc * 32 + lane) * BATCH + xoff];
    }
}

// out[t][o] = h_t . fc_w[o] + fc_b[o]
__global__ void fc_kernel(const float* __restrict__ fc_w,
                          const float* __restrict__ fc_b,
                          float* __restrict__ out)
{
    const int i = blockIdx.x * blockDim.x + threadIdx.x;
    if (i >= T_LEN * NOUT) return;
    const int t = i / NOUT;
    const int o = i - t * NOUT;
    const float* hrow = &g_hist[t * HID];
    float acc = fc_b[o];
    #pragma unroll
    for (int k = 0; k < HID; ++k)
        acc = fmaf(hrow[k], fc_w[o * HID + k], acc);
    out[i] = acc;
}

extern "C" void kernel_launch(void* const* d_in, const int* in_sizes, int n_in,
                              void* d_out, int out_size)
{
    const float* x    = (const float*)d_in[0];
    const float* w_ih = (const float*)d_in[1];
    const float* w_hh = (const float*)d_in[2];
    const float* b_ih = (const float*)d_in[3];
    const float* b_hh = (const float*)d_in[4];
    const float* fc_w = (const float*)d_in[5];
    const float* fc_b = (const float*)d_in[6];
    float* out = (float*)d_out;

    gru_seq_kernel<<<1, 32>>>(x, w_ih, w_hh, b_ih, b_hh);

    const int n = T_LEN * NOUT;
    fc_kernel<<<(n + 255) / 256, 256>>>(fc_w, fc_b, out);
}